// round 5
// baseline (speedup 1.0000x reference)
#include <cuda_runtime.h>
#include <cuda_bf16.h>
#include <math.h>
#include <stdint.h>

#define LL    8192
#define DIM   256
#define DI    512
#define DCONV 4
#define NS    16
#define DTR   16
#define NE    4
#define INNER 512
#define HOR   32
#define NBLK  8
#define EPSV  1e-3f

#define NCH 128   // scan chunks
#define CL  64    // chunk length (NCH*CL == LL)

// ---------------- scratch (static device allocations only) ----------------
__device__ float g_h   [LL*DIM];
__device__ float g_hn  [LL*DIM];
__device__ float g_xT  [LL*DIM];
__device__ float g_xr  [LL*2*DI];
__device__ float g_xc  [LL*DI];
__device__ float g_xdbl[LL*(DTR+2*NS)];
__device__ float g_delta[LL*DI];
__device__ float g_y   [LL*DI];
__device__ float g_moe [LL*DIM];
__device__ float g_w   [LL*NE];
__device__ float g_cs  [NCH*DI*NS];
__device__ float g_sd  [NCH*DI];
__device__ float g_init[NCH*DI*NS];
__device__ float g_gu  [LL*NE*INNER];   // merged MoE gate/up buffer (L x 2048)

__device__ __forceinline__ float siluf(float x) { return x / (1.f + expf(-x)); }

__device__ __forceinline__ void mma_tf32(float c[4], const unsigned int a[4], const unsigned int b[2]) {
    asm volatile("mma.sync.aligned.m16n8k8.row.col.f32.tf32.tf32.f32 "
        "{%0,%1,%2,%3}, {%4,%5,%6,%7}, {%8,%9}, {%0,%1,%2,%3};"
        : "+f"(c[0]), "+f"(c[1]), "+f"(c[2]), "+f"(c[3])
        : "r"(a[0]), "r"(a[1]), "r"(a[2]), "r"(a[3]), "r"(b[0]), "r"(b[1]));
}

__device__ __forceinline__ void cp_async16(void* dst, const void* src) {
    unsigned int d = (unsigned int)__cvta_generic_to_shared(dst);
    asm volatile("cp.async.cg.shared.global [%0], [%1], 16;\n" :: "r"(d), "l"(src));
}
__device__ __forceinline__ void cp_commit() { asm volatile("cp.async.commit_group;\n"); }
__device__ __forceinline__ void cp_wait0()  { asm volatile("cp.async.wait_group 0;\n"); }
__device__ __forceinline__ void cp_wait1()  { asm volatile("cp.async.wait_group 1;\n"); }

// ---------------- transpose x (DIM,L) -> xT (L,DIM) ----------------
__global__ void transpose_kernel(const float* __restrict__ x, float* __restrict__ xT)
{
    __shared__ float tile[32][33];
    int bx = blockIdx.x * 32;
    int by = blockIdx.y * 32;
    int tx = threadIdx.x, ty = threadIdx.y; // 32 x 8
    #pragma unroll
    for (int i = 0; i < 32; i += 8)
        tile[ty + i][tx] = x[(by + ty + i) * LL + bx + tx];
    __syncthreads();
    #pragma unroll
    for (int i = 0; i < 32; i += 8)
        xT[(bx + ty + i) * DIM + by + tx] = tile[tx][ty + i];
}

// ---------------- tensor-core GEMM: C[M,N] = epi(A[M,K](lda) @ W[N,K]^T) ----------------
// modes: 0 store, 1 silu store, 2 add residual R, 6 C = silu(C)*acc*rs[m*rsStride + (bn>>9)]
// wMoE: B matrix is 4 expert slices dp[e][n][kk], e = k>>9, kk = k&511 (K=2048)
// 128x64x32 tiles, 3-stage cp.async ring, one __syncthreads per K-step.
#define BM 128
#define BN 64
#define BK 32
#define SST 36
#define NSTG 3
#define GEMM_SMEM (NSTG*(BM+BN)*SST*4)

extern __shared__ unsigned int smem_u[];

__global__ __launch_bounds__(256)
void gemm_tc(const float* __restrict__ A, const float* __restrict__ W,
             float* __restrict__ C, const float* __restrict__ R,
             const float* __restrict__ rs, int rsStride, int lda,
             int M, int N, int K, int mode, int wMoE)
{
    unsigned int* As = smem_u;                      // [NSTG][BM*SST]
    unsigned int* Bs = smem_u + NSTG * BM * SST;    // [NSTG][BN*SST]
    int bm = blockIdx.y * BM;
    int bn = blockIdx.x * BN;
    int tid = threadIdx.x;
    int lane = tid & 31;
    int warp = tid >> 5;
    int wm = (warp & 3) * 32;
    int wn = (warp >> 2) * 32;

    float acc[2][4][4];
    #pragma unroll
    for (int mt = 0; mt < 2; mt++)
        #pragma unroll
        for (int nt = 0; nt < 4; nt++)
            #pragma unroll
            for (int q = 0; q < 4; q++) acc[mt][nt][q] = 0.f;

    auto issue = [&](int k0, int st) {
        unsigned int* Ab = As + st * BM * SST;
        unsigned int* Bb = Bs + st * BN * SST;
        #pragma unroll
        for (int q = 0; q < 4; q++) {               // A: 1024 granules of 16B
            int g = q * 256 + tid;
            int r = g >> 3, c4 = g & 7;
            cp_async16(Ab + r * SST + c4 * 4,
                       A + (size_t)(bm + r) * lda + k0 + c4 * 4);
        }
        const float* Wb;
        int wst;
        if (wMoE) {
            int e = k0 >> 9;
            Wb = W + (size_t)e * DIM * INNER + (k0 & 511);
            wst = INNER;
        } else {
            Wb = W + k0;
            wst = K;
        }
        #pragma unroll
        for (int q = 0; q < 2; q++) {               // B: 512 granules
            int g = q * 256 + tid;
            int r = g >> 3, c4 = g & 7;
            int rn = bn + r; if (rn >= N) rn = N - 1;
            cp_async16(Bb + r * SST + c4 * 4,
                       Wb + (size_t)rn * wst + c4 * 4);
        }
        cp_commit();
    };

    int nsteps = K / BK;
    issue(0, 0);
    issue(BK, 1);

    int rq = lane >> 2;
    int cq = lane & 3;

    for (int s = 0; s < nsteps; s++) {
        if (s + 1 < nsteps) cp_wait1(); else cp_wait0();
        __syncthreads();
        if (s + 2 < nsteps) issue((s + 2) * BK, (s + 2) % NSTG);

        int st = s % NSTG;
        const unsigned int* Ab = As + st * BM * SST;
        const unsigned int* Bb = Bs + st * BN * SST;
        #pragma unroll
        for (int kk = 0; kk < 4; kk++) {
            int kb = kk * 8 + cq;
            unsigned int a[2][4], b[4][2];
            #pragma unroll
            for (int mt = 0; mt < 2; mt++) {
                int rb = wm + mt * 16 + rq;
                a[mt][0] = Ab[rb * SST + kb];
                a[mt][1] = Ab[(rb + 8) * SST + kb];
                a[mt][2] = Ab[rb * SST + kb + 4];
                a[mt][3] = Ab[(rb + 8) * SST + kb + 4];
            }
            #pragma unroll
            for (int nt = 0; nt < 4; nt++) {
                int cb = wn + nt * 8 + rq;
                b[nt][0] = Bb[cb * SST + kb];
                b[nt][1] = Bb[cb * SST + kb + 4];
            }
            #pragma unroll
            for (int mt = 0; mt < 2; mt++)
                #pragma unroll
                for (int nt = 0; nt < 4; nt++)
                    mma_tf32(acc[mt][nt], a[mt], b[nt]);
        }
    }

    // epilogue
    int cc = cq * 2;
    int eIdx = bn >> 9;   // expert slice for mode 6
    #pragma unroll
    for (int mt = 0; mt < 2; mt++) {
        #pragma unroll
        for (int half = 0; half < 2; half++) {
            int m = bm + wm + mt * 16 + rq + half * 8;
            float rsv = (mode == 6) ? rs[m * rsStride + eIdx] : 0.f;
            #pragma unroll
            for (int nt = 0; nt < 4; nt++) {
                int n = bn + wn + nt * 8 + cc;
                if (n < N) {
                    size_t o = (size_t)m * N + n;
                    float v0 = acc[mt][nt][half * 2 + 0];
                    float v1 = acc[mt][nt][half * 2 + 1];
                    if (mode == 0) {
                        C[o] = v0; C[o + 1] = v1;
                    } else if (mode == 1) {
                        C[o]     = v0 / (1.f + expf(-v0));
                        C[o + 1] = v1 / (1.f + expf(-v1));
                    } else if (mode == 2) {
                        C[o] = v0 + R[o]; C[o + 1] = v1 + R[o + 1];
                    } else { // mode 6: C = silu(C)*acc*w
                        float g0 = C[o], g1 = C[o + 1];
                        C[o]     = (g0 / (1.f + expf(-g0))) * v0 * rsv;
                        C[o + 1] = (g1 / (1.f + expf(-g1))) * v1 * rsv;
                    }
                }
            }
        }
    }
}

// ---------------- rmsnorm over rows of 256 (optional residual add) ----------------
__global__ void rmsnorm_kernel(const float* __restrict__ in, const float* __restrict__ w,
                               const float* __restrict__ addres, float* __restrict__ out)
{
    int l = blockIdx.x;
    int t = threadIdx.x; // 256
    float v = in[l * DIM + t];
    __shared__ float red[8];
    float s = v * v;
    #pragma unroll
    for (int o = 16; o > 0; o >>= 1) s += __shfl_xor_sync(0xffffffffu, s, o);
    if ((t & 31) == 0) red[t >> 5] = s;
    __syncthreads();
    if (t < 8) {
        float x2 = red[t];
        #pragma unroll
        for (int o = 4; o > 0; o >>= 1) x2 += __shfl_xor_sync(0xffu, x2, o);
        if (t == 0) red[0] = x2;
    }
    __syncthreads();
    float rms = rsqrtf(red[0] / (float)DIM + EPSV);
    float r = w[t] * v * rms;
    if (addres) r += addres[l * DIM + t];
    out[l * DIM + t] = r;
}

// ---------------- causal depthwise conv(4) + bias + silu ----------------
__global__ void conv_kernel(const float* __restrict__ xr, const float* __restrict__ cw,
                            const float* __restrict__ cb, float* __restrict__ xc)
{
    int idx = blockIdx.x * blockDim.x + threadIdx.x;
    if (idx >= LL * DI) return;
    int c = idx % DI, l = idx / DI;
    float w0 = cw[c * 4 + 0], w1 = cw[c * 4 + 1], w2 = cw[c * 4 + 2], w3 = cw[c * 4 + 3];
    float acc = cb[c];
    if (l >= 3) acc += xr[(size_t)(l - 3) * (2 * DI) + c] * w0;
    if (l >= 2) acc += xr[(size_t)(l - 2) * (2 * DI) + c] * w1;
    if (l >= 1) acc += xr[(size_t)(l - 1) * (2 * DI) + c] * w2;
    acc += xr[(size_t)l * (2 * DI) + c] * w3;
    xc[idx] = siluf(acc);
}

// ---------------- delta = softplus(dr @ dtw^T + dtb) ----------------
__global__ void delta_kernel(const float* __restrict__ xdbl, const float* __restrict__ dtw,
                             const float* __restrict__ dtb, float* __restrict__ delta)
{
    int l = blockIdx.x;
    __shared__ float dr[DTR];
    if (threadIdx.x < DTR) dr[threadIdx.x] = xdbl[l * 48 + threadIdx.x];
    __syncthreads();
    for (int d = threadIdx.x; d < DI; d += blockDim.x) {
        float acc = dtb[d];
        #pragma unroll
        for (int r = 0; r < DTR; r++) acc += dr[r] * dtw[d * DTR + r];
        float sp = (acc > 20.f) ? acc : log1pf(expf(acc));
        delta[(size_t)l * DI + d] = sp;
    }
}

// ---------------- gate: scores, top-2 softmax weights ----------------
__global__ void gate_kernel(const float* __restrict__ h, const float* __restrict__ gw,
                            float* __restrict__ wout)
{
    __shared__ float sgw[NE * DIM];
    int tid = threadIdx.x; // 256
    for (int i = tid; i < NE * DIM; i += 256) sgw[i] = gw[i];
    __syncthreads();
    int warp = tid >> 5, lane = tid & 31;
    int t = blockIdx.x * 8 + warp;
    float acc[NE] = {0.f, 0.f, 0.f, 0.f};
    for (int k = lane; k < DIM; k += 32) {
        float hv = h[(size_t)t * DIM + k];
        #pragma unroll
        for (int e = 0; e < NE; e++) acc[e] += hv * sgw[e * DIM + k];
    }
    #pragma unroll
    for (int e = 0; e < NE; e++)
        #pragma unroll
        for (int o = 16; o > 0; o >>= 1) acc[e] += __shfl_xor_sync(0xffffffffu, acc[e], o);
    if (lane == 0) {
        int i1 = 0; float v1 = acc[0];
        for (int e = 1; e < NE; e++) if (acc[e] > v1) { v1 = acc[e]; i1 = e; }
        int i2 = -1; float v2 = -1e30f;
        for (int e = 0; e < NE; e++) if (e != i1 && acc[e] > v2) { v2 = acc[e]; i2 = e; }
        float ew = expf(v2 - v1);
        float w1 = 1.f / (1.f + ew), w2 = ew / (1.f + ew);
        float w[NE] = {0.f, 0.f, 0.f, 0.f};
        w[i1] = w1; w[i2] = w2;
        #pragma unroll
        for (int e = 0; e < NE; e++) wout[t * NE + e] = w[e];
    }
}

// ---------------- chunked selective scan ----------------
__global__ void scan_p1(const float* __restrict__ delta, const float* __restrict__ xc,
                        const float* __restrict__ xdbl, const float* __restrict__ Alog,
                        float* __restrict__ cs, float* __restrict__ sd)
{
    int b = blockIdx.x;          // NCH * (DI/8)
    int chunk = b >> 6;
    int dg = b & 63;
    int tid = threadIdx.x;       // 128 = 8 d x 16 n
    int dl = tid >> 4, n = tid & 15;
    int d = dg * 8 + dl;
    float Acoef = -__expf(Alog[d * NS + n]);
    float s = 0.f, sdl = 0.f;
    int l0 = chunk * CL;
    for (int i = 0; i < CL; i++) {
        int l = l0 + i;
        float dt = delta[(size_t)l * DI + d];
        float x  = xc[(size_t)l * DI + d];
        float Bv = xdbl[l * 48 + DTR + n];
        s = __expf(dt * Acoef) * s + dt * Bv * x;
        sdl += dt;
    }
    cs[((size_t)chunk * DI + d) * NS + n] = s;
    if (n == 0) sd[chunk * DI + d] = sdl;
}

__global__ void scan_p2(const float* __restrict__ Alog, const float* __restrict__ cs,
                        const float* __restrict__ sd, float* __restrict__ init)
{
    int idx = blockIdx.x * blockDim.x + threadIdx.x; // DI*NS = 8192
    int d = idx >> 4, n = idx & 15;
    float Acoef = -__expf(Alog[d * NS + n]);
    float S = 0.f;
    for (int c = 0; c < NCH; c++) {
        init[((size_t)c * DI + d) * NS + n] = S;
        S = __expf(Acoef * sd[c * DI + d]) * S + cs[((size_t)c * DI + d) * NS + n];
    }
}

__global__ void scan_p3(const float* __restrict__ delta, const float* __restrict__ xc,
                        const float* __restrict__ xdbl, const float* __restrict__ Alog,
                        const float* __restrict__ init, const float* __restrict__ Dp,
                        const float* __restrict__ xr, float* __restrict__ y)
{
    int b = blockIdx.x;
    int chunk = b >> 6;
    int dg = b & 63;
    int tid = threadIdx.x;
    int dl = tid >> 4, n = tid & 15;
    int d = dg * 8 + dl;
    float Acoef = -__expf(Alog[d * NS + n]);
    float s = init[((size_t)chunk * DI + d) * NS + n];
    float Dv = Dp[d];
    int l0 = chunk * CL;
    for (int i = 0; i < CL; i++) {
        int l = l0 + i;
        float dt = delta[(size_t)l * DI + d];
        float x  = xc[(size_t)l * DI + d];
        float Bv = xdbl[l * 48 + DTR + n];
        float Cv = xdbl[l * 48 + DTR + NS + n];
        s = __expf(dt * Acoef) * s + dt * Bv * x;
        float part = s * Cv;
        #pragma unroll
        for (int o = 1; o < 16; o <<= 1)
            part += __shfl_xor_sync(0xffffffffu, part, o, 16);
        if (n == 0) {
            float res = xr[(size_t)l * (2 * DI) + DI + d];
            y[(size_t)l * DI + d] = (part + x * Dv) * siluf(res);
        }
    }
}

// ---------------- head2: out[o,l] = sigmoid(a[l,:] . w2[o,:]) ----------------
__global__ void head2_kernel(const float* __restrict__ a, const float* __restrict__ w2,
                             float* __restrict__ out)
{
    int idx = blockIdx.x * blockDim.x + threadIdx.x; // LL*HOR
    int o = idx & 31, l = idx >> 5;
    const float* ar = a + (size_t)l * DIM;
    const float* wr = w2 + (size_t)o * DIM;
    float acc = 0.f;
    #pragma unroll 8
    for (int k = 0; k < DIM; k++) acc += ar[k] * wr[k];
    out[(size_t)o * LL + l] = 1.f / (1.f + expf(-acc));
}

// ---------------- host orchestration ----------------
extern "C" void kernel_launch(void* const* d_in, const int* in_sizes, int n_in,
                              void* d_out, int out_size)
{
    const float* x         = (const float*)d_in[0];
    const float* lin_w     = (const float*)d_in[1];
    const float* in_proj_w = (const float*)d_in[2];
    const float* conv_w    = (const float*)d_in[3];
    const float* conv_b    = (const float*)d_in[4];
    const float* x_proj_w  = (const float*)d_in[5];
    const float* dt_proj_w = (const float*)d_in[6];
    const float* dt_proj_b = (const float*)d_in[7];
    const float* A_log     = (const float*)d_in[8];
    const float* D_param   = (const float*)d_in[9];
    const float* out_proj_w= (const float*)d_in[10];
    const float* gate_w    = (const float*)d_in[11];
    const float* gproj_w   = (const float*)d_in[12];
    const float* uproj_w   = (const float*)d_in[13];
    const float* dproj_w   = (const float*)d_in[14];
    const float* rms_a_w   = (const float*)d_in[15];
    const float* rms_f_w   = (const float*)d_in[16];
    const float* head_w1   = (const float*)d_in[17];
    const float* head_w2   = (const float*)d_in[18];
    float* out = (float*)d_out;

    float *h, *hn, *xT, *xr, *xc, *xdbl, *delta, *y, *moe, *w, *cs, *sd, *init, *gu;
    cudaGetSymbolAddress((void**)&h,    g_h);
    cudaGetSymbolAddress((void**)&hn,   g_hn);
    cudaGetSymbolAddress((void**)&xT,   g_xT);
    cudaGetSymbolAddress((void**)&xr,   g_xr);
    cudaGetSymbolAddress((void**)&xc,   g_xc);
    cudaGetSymbolAddress((void**)&xdbl, g_xdbl);
    cudaGetSymbolAddress((void**)&delta,g_delta);
    cudaGetSymbolAddress((void**)&y,    g_y);
    cudaGetSymbolAddress((void**)&moe,  g_moe);
    cudaGetSymbolAddress((void**)&w,    g_w);
    cudaGetSymbolAddress((void**)&cs,   g_cs);
    cudaGetSymbolAddress((void**)&sd,   g_sd);
    cudaGetSymbolAddress((void**)&init, g_init);
    cudaGetSymbolAddress((void**)&gu,   g_gu);

    static bool attr_set = false;
    if (!attr_set) {
        cudaFuncSetAttribute(gemm_tc, cudaFuncAttributeMaxDynamicSharedMemorySize, GEMM_SMEM);
        attr_set = true;
    }

    auto gemm = [&](const float* A, const float* W, float* C, const float* R,
                    const float* rs, int rsStride, int lda, int N, int K, int mode, int wMoE) {
        dim3 grid((N + BN - 1) / BN, LL / BM);
        gemm_tc<<<grid, 256, GEMM_SMEM>>>(A, W, C, R, rs, rsStride, lda, LL, N, K, mode, wMoE);
    };

    // h = x.T @ lin_w.T
    transpose_kernel<<<dim3(LL / 32, DIM / 32), dim3(32, 8)>>>(x, xT);
    gemm(xT, lin_w, h, nullptr, nullptr, 0, DIM, DIM, DIM, 0, 0);

    for (int i = 0; i < NBLK; i++) {
        // ---- mamba ----
        rmsnorm_kernel<<<LL, DIM>>>(h, rms_a_w, nullptr, hn);
        gemm(hn, in_proj_w + (size_t)i * 2 * DI * DIM, xr, nullptr, nullptr, 0, DIM, 2 * DI, DIM, 0, 0);
        conv_kernel<<<(LL * DI + 255) / 256, 256>>>(xr, conv_w + (size_t)i * DI * DCONV,
                                                    conv_b + (size_t)i * DI, xc);
        gemm(xc, x_proj_w + (size_t)i * 48 * DI, xdbl, nullptr, nullptr, 0, DI, 48, DI, 0, 0);
        delta_kernel<<<LL, 256>>>(xdbl, dt_proj_w + (size_t)i * DI * DTR,
                                  dt_proj_b + (size_t)i * DI, delta);
        const float* Alog_i = A_log + (size_t)i * DI * NS;
        scan_p1<<<NCH * (DI / 8), 128>>>(delta, xc, xdbl, Alog_i, cs, sd);
        scan_p2<<<DI * NS / 256, 256>>>(Alog_i, cs, sd, init);
        scan_p3<<<NCH * (DI / 8), 128>>>(delta, xc, xdbl, Alog_i, init,
                                         D_param + (size_t)i * DI, xr, y);
        // h = out_proj(y) + h (residual)
        gemm(y, out_proj_w + (size_t)i * DIM * DI, h, h, nullptr, 0, DI, DIM, DI, 2, 0);

        // ---- MoE ----
        gate_kernel<<<LL / 8, 256>>>(h, gate_w + (size_t)i * NE * DIM, w);
        // gu = h @ Gall^T (raw)
        gemm(h, gproj_w + (size_t)i * NE * INNER * DIM, gu, nullptr, nullptr, 0,
             DIM, NE * INNER, DIM, 0, 0);
        // gu = silu(gu) * (h @ Uall^T) * w[t, e]
        gemm(h, uproj_w + (size_t)i * NE * INNER * DIM, gu, nullptr, w, NE,
             DIM, NE * INNER, DIM, 6, 0);
        // moe = gu @ Dall^T  (K = 2048, expert-sliced B)
        gemm(gu, dproj_w + (size_t)i * NE * DIM * INNER, moe, nullptr, nullptr, 0,
             NE * INNER, DIM, NE * INNER, 0, 1);
        // h = rmsnorm(moe) + h
        rmsnorm_kernel<<<LL, DIM>>>(moe, rms_f_w, h, h);
    }

    // head
    gemm(h, lin_w, hn, nullptr, nullptr, 0, DIM, DIM, DIM, 0, 0);
    gemm(hn, head_w1, xT, nullptr, nullptr, 0, DIM, DIM, DIM, 1, 0);
    head2_kernel<<<LL * HOR / 256, 256>>>(xT, head_w2, out);
}

// round 7
// speedup vs baseline: 1.2162x; 1.2162x over previous
#include <cuda_runtime.h>
#include <cuda_bf16.h>
#include <math.h>
#include <stdint.h>

#define LL    8192
#define DIM   256
#define DI    512
#define DCONV 4
#define NS    16
#define DTR   16
#define NE    4
#define INNER 512
#define HOR   32
#define NBLK  8
#define EPSV  1e-3f

#define NCH 128
#define CL  64

typedef __nv_bfloat16 bf16;
typedef __nv_bfloat162 bf162;

// ---------------- fp32 scratch ----------------
__device__ float g_h   [LL*DIM];
__device__ float g_xT  [LL*DIM];
__device__ float g_xr  [LL*2*DI];
__device__ float g_xc  [LL*DI];
__device__ float g_xdbl[LL*(DTR+2*NS)];
__device__ float g_delta[LL*DI];
__device__ float g_gf  [LL*NE*INNER];   // MoE gate raw (fp32)
__device__ float g_moe [LL*DIM];
__device__ float g_w   [LL*NE];
__device__ float g_cs  [NCH*DI*NS];
__device__ float g_sd  [NCH*DI];
__device__ float g_init[NCH*DI*NS];
// ---------------- bf16 activation scratch ----------------
__device__ bf16 g_hb  [LL*DIM];
__device__ bf16 g_hnb [LL*DIM];
__device__ bf16 g_xTb [LL*DIM];
__device__ bf16 g_xcb [LL*DI];
__device__ bf16 g_yb  [LL*DI];
__device__ bf16 g_gub [LL*NE*INNER];
// ---------------- bf16 weights ----------------
__device__ bf16 g_linb [DIM*DIM];
__device__ bf16 g_inpb [NBLK*2*DI*DIM];
__device__ bf16 g_xpb  [NBLK*(DTR+2*NS)*DI];
__device__ bf16 g_outpb[NBLK*DIM*DI];
__device__ bf16 g_gpb  [NBLK*NE*INNER*DIM];
__device__ bf16 g_upb  [NBLK*NE*INNER*DIM];
__device__ bf16 g_dpb  [NBLK*NE*DIM*INNER];
__device__ bf16 g_hw1b [DIM*DIM];

__device__ __forceinline__ float siluf(float x) { return x / (1.f + expf(-x)); }

__device__ __forceinline__ void mma_bf16(float c[4], const unsigned int a[4], const unsigned int b[2]) {
    asm volatile("mma.sync.aligned.m16n8k16.row.col.f32.bf16.bf16.f32 "
        "{%0,%1,%2,%3}, {%4,%5,%6,%7}, {%8,%9}, {%0,%1,%2,%3};"
        : "+f"(c[0]), "+f"(c[1]), "+f"(c[2]), "+f"(c[3])
        : "r"(a[0]), "r"(a[1]), "r"(a[2]), "r"(a[3]), "r"(b[0]), "r"(b[1]));
}

__device__ __forceinline__ void cp_async16(void* dst, const void* src) {
    unsigned int d = (unsigned int)__cvta_generic_to_shared(dst);
    asm volatile("cp.async.cg.shared.global [%0], [%1], 16;\n" :: "r"(d), "l"(src));
}
__device__ __forceinline__ void cp_commit() { asm volatile("cp.async.commit_group;\n"); }
__device__ __forceinline__ void cp_wait0()  { asm volatile("cp.async.wait_group 0;\n"); }
__device__ __forceinline__ void cp_wait1()  { asm volatile("cp.async.wait_group 1;\n"); }

// ---------------- fp32 -> bf16 conversion ----------------
__global__ void f2b_kernel(const float* __restrict__ in, bf16* __restrict__ out, int n)
{
    int i = (blockIdx.x * blockDim.x + threadIdx.x) * 4;
    if (i < n) {
        float4 v = *(const float4*)(in + i);
        bf162 lo = __float22bfloat162_rn(make_float2(v.x, v.y));
        bf162 hi = __float22bfloat162_rn(make_float2(v.z, v.w));
        *(bf162*)(out + i) = lo;
        *(bf162*)(out + i + 2) = hi;
    }
}

// ---------------- transpose x (DIM,L) -> xT (L,DIM) bf16 ----------------
__global__ void transpose_kernel(const float* __restrict__ x, bf16* __restrict__ xTb)
{
    __shared__ float tile[32][33];
    int bx = blockIdx.x * 32;
    int by = blockIdx.y * 32;
    int tx = threadIdx.x, ty = threadIdx.y;
    #pragma unroll
    for (int i = 0; i < 32; i += 8)
        tile[ty + i][tx] = x[(by + ty + i) * LL + bx + tx];
    __syncthreads();
    #pragma unroll
    for (int i = 0; i < 32; i += 8)
        xTb[(bx + ty + i) * DIM + by + tx] = __float2bfloat16(tile[tx][ty + i]);
}

// ---------------- bf16 tensor-core GEMM: C = epi(A[M,K](lda) @ W[N,K]^T) ----------------
// modes: 0 store, 1 silu store, 2 v+=R store, 6 Cb = bf16(silu(C)*v*rs[m*rsStride+(bn>>9)])
// fp32 C stores are guarded by C != nullptr; bf16 dup to Cb if Cb != nullptr.
// wMoE: B is 4 expert slices dp[e][n][k&511], e = k>>9 (K = 2048)
#define BM 128
#define BN 64
#define BK 32
#define ST 20              // u32 row stride (16 data + 4 pad)
#define NSTG 3
#define GEMM_SMEM (NSTG*(BM+BN)*ST*4)

extern __shared__ unsigned int smem_u[];

__global__ __launch_bounds__(256)
void gemm_bf(const bf16* __restrict__ A, const bf16* __restrict__ W,
             float* __restrict__ C, bf16* __restrict__ Cb,
             const float* __restrict__ R,
             const float* __restrict__ rs, int rsStride, int lda,
             int M, int N, int K, int mode, int wMoE)
{
    unsigned int* As = smem_u;                    // [NSTG][BM*ST]
    unsigned int* Bs = smem_u + NSTG * BM * ST;   // [NSTG][BN*ST]
    int bm = blockIdx.y * BM;
    int bn = blockIdx.x * BN;
    int tid = threadIdx.x;
    int lane = tid & 31;
    int warp = tid >> 5;
    int wm = (warp & 3) * 32;
    int wn = (warp >> 2) * 32;

    float acc[2][4][4];
    #pragma unroll
    for (int mt = 0; mt < 2; mt++)
        #pragma unroll
        for (int nt = 0; nt < 4; nt++)
            #pragma unroll
            for (int q = 0; q < 4; q++) acc[mt][nt][q] = 0.f;

    auto issue = [&](int k0, int st) {
        unsigned int* Ab = As + st * BM * ST;
        unsigned int* Bb = Bs + st * BN * ST;
        #pragma unroll
        for (int q = 0; q < 2; q++) {            // A: 128 rows x 4 granules = 512
            int g = q * 256 + tid;
            int r = g >> 2, c4 = g & 3;
            cp_async16(Ab + r * ST + c4 * 4,
                       A + (size_t)(bm + r) * lda + k0 + c4 * 8);
        }
        const bf16* Wb;
        int wst;
        if (wMoE) {
            int e = k0 >> 9;
            Wb = W + (size_t)e * DIM * INNER + (k0 & 511);
            wst = INNER;
        } else {
            Wb = W + k0;
            wst = K;
        }
        {                                         // B: 64 rows x 4 granules = 256
            int r = tid >> 2, c4 = tid & 3;
            int rn = bn + r; if (rn >= N) rn = N - 1;
            cp_async16(Bb + r * ST + c4 * 4,
                       Wb + (size_t)rn * wst + c4 * 8);
        }
        cp_commit();
    };

    int nsteps = K / BK;
    issue(0, 0);
    issue(BK, 1);

    int rq = lane >> 2;
    int cq = lane & 3;

    for (int s = 0; s < nsteps; s++) {
        if (s + 1 < nsteps) cp_wait1(); else cp_wait0();
        __syncthreads();
        if (s + 2 < nsteps) issue((s + 2) * BK, (s + 2) % NSTG);

        int st = s % NSTG;
        const unsigned int* Ab = As + st * BM * ST;
        const unsigned int* Bb = Bs + st * BN * ST;
        #pragma unroll
        for (int kk = 0; kk < 2; kk++) {
            int ko = kk * 8;
            unsigned int a[2][4], b[4][2];
            #pragma unroll
            for (int mt = 0; mt < 2; mt++) {
                int rb = wm + mt * 16 + rq;
                a[mt][0] = Ab[rb * ST + ko + cq];
                a[mt][1] = Ab[(rb + 8) * ST + ko + cq];
                a[mt][2] = Ab[rb * ST + ko + cq + 4];
                a[mt][3] = Ab[(rb + 8) * ST + ko + cq + 4];
            }
            #pragma unroll
            for (int nt = 0; nt < 4; nt++) {
                int cb = wn + nt * 8 + rq;
                b[nt][0] = Bb[cb * ST + ko + cq];
                b[nt][1] = Bb[cb * ST + ko + cq + 4];
            }
            #pragma unroll
            for (int mt = 0; mt < 2; mt++)
                #pragma unroll
                for (int nt = 0; nt < 4; nt++)
                    mma_bf16(acc[mt][nt], a[mt], b[nt]);
        }
    }

    // epilogue
    int cc = cq * 2;
    int eIdx = bn >> 9;
    #pragma unroll
    for (int mt = 0; mt < 2; mt++) {
        #pragma unroll
        for (int half = 0; half < 2; half++) {
            int m = bm + wm + mt * 16 + rq + half * 8;
            float rsv = (mode == 6) ? rs[m * rsStride + eIdx] : 0.f;
            #pragma unroll
            for (int nt = 0; nt < 4; nt++) {
                int n = bn + wn + nt * 8 + cc;
                if (n < N) {
                    size_t o = (size_t)m * N + n;
                    float v0 = acc[mt][nt][half * 2 + 0];
                    float v1 = acc[mt][nt][half * 2 + 1];
                    if (mode == 1) {
                        v0 = v0 / (1.f + expf(-v0));
                        v1 = v1 / (1.f + expf(-v1));
                    } else if (mode == 2) {
                        v0 += R[o]; v1 += R[o + 1];
                    } else if (mode == 6) {
                        float g0 = C[o], g1 = C[o + 1];
                        v0 = (g0 / (1.f + expf(-g0))) * v0 * rsv;
                        v1 = (g1 / (1.f + expf(-g1))) * v1 * rsv;
                    }
                    if (C && mode != 6) { C[o] = v0; C[o + 1] = v1; }
                    if (Cb)
                        *(bf162*)(Cb + o) = __float22bfloat162_rn(make_float2(v0, v1));
                }
            }
        }
    }
}

// ---------------- rmsnorm: fp32 out optional, bf16 out optional ----------------
__global__ void rmsnorm_kernel(const float* __restrict__ in, const float* __restrict__ w,
                               const float* __restrict__ addres,
                               float* __restrict__ out, bf16* __restrict__ outb)
{
    int l = blockIdx.x;
    int t = threadIdx.x;
    float v = in[l * DIM + t];
    __shared__ float red[8];
    float s = v * v;
    #pragma unroll
    for (int o = 16; o > 0; o >>= 1) s += __shfl_xor_sync(0xffffffffu, s, o);
    if ((t & 31) == 0) red[t >> 5] = s;
    __syncthreads();
    if (t < 8) {
        float x2 = red[t];
        #pragma unroll
        for (int o = 4; o > 0; o >>= 1) x2 += __shfl_xor_sync(0xffu, x2, o);
        if (t == 0) red[0] = x2;
    }
    __syncthreads();
    float rms = rsqrtf(red[0] / (float)DIM + EPSV);
    float r = w[t] * v * rms;
    if (addres) r += addres[l * DIM + t];
    if (out)  out[l * DIM + t] = r;
    if (outb) outb[l * DIM + t] = __float2bfloat16(r);
}

// ---------------- causal depthwise conv(4) + bias + silu (fp32 + bf16 out) ----------------
__global__ void conv_kernel(const float* __restrict__ xr, const float* __restrict__ cw,
                            const float* __restrict__ cb,
                            float* __restrict__ xc, bf16* __restrict__ xcb)
{
    int idx = blockIdx.x * blockDim.x + threadIdx.x;
    if (idx >= LL * DI) return;
    int c = idx % DI, l = idx / DI;
    float w0 = cw[c * 4 + 0], w1 = cw[c * 4 + 1], w2 = cw[c * 4 + 2], w3 = cw[c * 4 + 3];
    float acc = cb[c];
    if (l >= 3) acc += xr[(size_t)(l - 3) * (2 * DI) + c] * w0;
    if (l >= 2) acc += xr[(size_t)(l - 2) * (2 * DI) + c] * w1;
    if (l >= 1) acc += xr[(size_t)(l - 1) * (2 * DI) + c] * w2;
    acc += xr[(size_t)l * (2 * DI) + c] * w3;
    float r = siluf(acc);
    xc[idx] = r;
    xcb[idx] = __float2bfloat16(r);
}

// ---------------- delta = softplus(dr @ dtw^T + dtb) ----------------
__global__ void delta_kernel(const float* __restrict__ xdbl, const float* __restrict__ dtw,
                             const float* __restrict__ dtb, float* __restrict__ delta)
{
    int l = blockIdx.x;
    __shared__ float dr[DTR];
    if (threadIdx.x < DTR) dr[threadIdx.x] = xdbl[l * 48 + threadIdx.x];
    __syncthreads();
    for (int d = threadIdx.x; d < DI; d += blockDim.x) {
        float acc = dtb[d];
        #pragma unroll
        for (int r = 0; r < DTR; r++) acc += dr[r] * dtw[d * DTR + r];
        float sp = (acc > 20.f) ? acc : log1pf(expf(acc));
        delta[(size_t)l * DI + d] = sp;
    }
}

// ---------------- gate: scores, top-2 softmax weights ----------------
__global__ void gate_kernel(const float* __restrict__ h, const float* __restrict__ gw,
                            float* __restrict__ wout)
{
    __shared__ float sgw[NE * DIM];
    int tid = threadIdx.x;
    for (int i = tid; i < NE * DIM; i += 256) sgw[i] = gw[i];
    __syncthreads();
    int warp = tid >> 5, lane = tid & 31;
    int t = blockIdx.x * 8 + warp;
    float acc[NE] = {0.f, 0.f, 0.f, 0.f};
    for (int k = lane; k < DIM; k += 32) {
        float hv = h[(size_t)t * DIM + k];
        #pragma unroll
        for (int e = 0; e < NE; e++) acc[e] += hv * sgw[e * DIM + k];
    }
    #pragma unroll
    for (int e = 0; e < NE; e++)
        #pragma unroll
        for (int o = 16; o > 0; o >>= 1) acc[e] += __shfl_xor_sync(0xffffffffu, acc[e], o);
    if (lane == 0) {
        int i1 = 0; float v1 = acc[0];
        for (int e = 1; e < NE; e++) if (acc[e] > v1) { v1 = acc[e]; i1 = e; }
        int i2 = -1; float v2 = -1e30f;
        for (int e = 0; e < NE; e++) if (e != i1 && acc[e] > v2) { v2 = acc[e]; i2 = e; }
        float ew = expf(v2 - v1);
        float w1 = 1.f / (1.f + ew), w2 = ew / (1.f + ew);
        float w[NE] = {0.f, 0.f, 0.f, 0.f};
        w[i1] = w1; w[i2] = w2;
        #pragma unroll
        for (int e = 0; e < NE; e++) wout[t * NE + e] = w[e];
    }
}

// ---------------- chunked selective scan ----------------
__global__ void scan_p1(const float* __restrict__ delta, const float* __restrict__ xc,
                        const float* __restrict__ xdbl, const float* __restrict__ Alog,
                        float* __restrict__ cs, float* __restrict__ sd)
{
    int b = blockIdx.x;
    int chunk = b >> 6;
    int dg = b & 63;
    int tid = threadIdx.x;
    int dl = tid >> 4, n = tid & 15;
    int d = dg * 8 + dl;
    float Acoef = -__expf(Alog[d * NS + n]);
    float s = 0.f, sdl = 0.f;
    int l0 = chunk * CL;
    for (int i = 0; i < CL; i++) {
        int l = l0 + i;
        float dt = delta[(size_t)l * DI + d];
        float x  = xc[(size_t)l * DI + d];
        float Bv = xdbl[l * 48 + DTR + n];
        s = __expf(dt * Acoef) * s + dt * Bv * x;
        sdl += dt;
    }
    cs[((size_t)chunk * DI + d) * NS + n] = s;
    if (n == 0) sd[chunk * DI + d] = sdl;
}

__global__ void scan_p2(const float* __restrict__ Alog, const float* __restrict__ cs,
                        const float* __restrict__ sd, float* __restrict__ init)
{
    int idx = blockIdx.x * blockDim.x + threadIdx.x;
    int d = idx >> 4, n = idx & 15;
    float Acoef = -__expf(Alog[d * NS + n]);
    float S = 0.f;
    for (int c = 0; c < NCH; c++) {
        init[((size_t)c * DI + d) * NS + n] = S;
        S = __expf(Acoef * sd[c * DI + d]) * S + cs[((size_t)c * DI + d) * NS + n];
    }
}

__global__ void scan_p3(const float* __restrict__ delta, const float* __restrict__ xc,
                        const float* __restrict__ xdbl, const float* __restrict__ Alog,
                        const float* __restrict__ init, const float* __restrict__ Dp,
                        const float* __restrict__ xr, bf16* __restrict__ yb)
{
    int b = blockIdx.x;
    int chunk = b >> 6;
    int dg = b & 63;
    int tid = threadIdx.x;
    int dl = tid >> 4, n = tid & 15;
    int d = dg * 8 + dl;
    float Acoef = -__expf(Alog[d * NS + n]);
    float s = init[((size_t)chunk * DI + d) * NS + n];
    float Dv = Dp[d];
    int l0 = chunk * CL;
    for (int i = 0; i < CL; i++) {
        int l = l0 + i;
        float dt = delta[(size_t)l * DI + d];
        float x  = xc[(size_t)l * DI + d];
        float Bv = xdbl[l * 48 + DTR + n];
        float Cv = xdbl[l * 48 + DTR + NS + n];
        s = __expf(dt * Acoef) * s + dt * Bv * x;
        float part = s * Cv;
        #pragma unroll
        for (int o = 1; o < 16; o <<= 1)
            part += __shfl_xor_sync(0xffffffffu, part, o, 16);
        if (n == 0) {
            float res = xr[(size_t)l * (2 * DI) + DI + d];
            yb[(size_t)l * DI + d] = __float2bfloat16((part + x * Dv) * siluf(res));
        }
    }
}

// ---------------- head2 ----------------
__global__ void head2_kernel(const float* __restrict__ a, const float* __restrict__ w2,
                             float* __restrict__ out)
{
    int idx = blockIdx.x * blockDim.x + threadIdx.x;
    int o = idx & 31, l = idx >> 5;
    const float* ar = a + (size_t)l * DIM;
    const float* wr = w2 + (size_t)o * DIM;
    float acc = 0.f;
    #pragma unroll 8
    for (int k = 0; k < DIM; k++) acc += ar[k] * wr[k];
    out[(size_t)o * LL + l] = 1.f / (1.f + expf(-acc));
}

// ---------------- host orchestration ----------------
extern "C" void kernel_launch(void* const* d_in, const int* in_sizes, int n_in,
                              void* d_out, int out_size)
{
    const float* x         = (const float*)d_in[0];
    const float* lin_w     = (const float*)d_in[1];
    const float* in_proj_w = (const float*)d_in[2];
    const float* conv_w    = (const float*)d_in[3];
    const float* conv_b    = (const float*)d_in[4];
    const float* x_proj_w  = (const float*)d_in[5];
    const float* dt_proj_w = (const float*)d_in[6];
    const float* dt_proj_b = (const float*)d_in[7];
    const float* A_log     = (const float*)d_in[8];
    const float* D_param   = (const float*)d_in[9];
    const float* out_proj_w= (const float*)d_in[10];
    const float* gate_w    = (const float*)d_in[11];
    const float* gproj_w   = (const float*)d_in[12];
    const float* uproj_w   = (const float*)d_in[13];
    const float* dproj_w   = (const float*)d_in[14];
    const float* rms_a_w   = (const float*)d_in[15];
    const float* rms_f_w   = (const float*)d_in[16];
    const float* head_w1   = (const float*)d_in[17];
    const float* head_w2   = (const float*)d_in[18];
    float* out = (float*)d_out;

    float *h, *xT, *xr, *xc, *xdbl, *delta, *gf, *moe, *w, *cs, *sd, *init;
    bf16 *hb, *hnb, *xTb, *xcb, *yb, *gub;
    bf16 *linb, *inpb, *xpb, *outpb, *gpb, *upb, *dpb, *hw1b;
    cudaGetSymbolAddress((void**)&h,    g_h);
    cudaGetSymbolAddress((void**)&xT,   g_xT);
    cudaGetSymbolAddress((void**)&xr,   g_xr);
    cudaGetSymbolAddress((void**)&xc,   g_xc);
    cudaGetSymbolAddress((void**)&xdbl, g_xdbl);
    cudaGetSymbolAddress((void**)&delta,g_delta);
    cudaGetSymbolAddress((void**)&gf,   g_gf);
    cudaGetSymbolAddress((void**)&moe,  g_moe);
    cudaGetSymbolAddress((void**)&w,    g_w);
    cudaGetSymbolAddress((void**)&cs,   g_cs);
    cudaGetSymbolAddress((void**)&sd,   g_sd);
    cudaGetSymbolAddress((void**)&init, g_init);
    cudaGetSymbolAddress((void**)&hb,   g_hb);
    cudaGetSymbolAddress((void**)&hnb,  g_hnb);
    cudaGetSymbolAddress((void**)&xTb,  g_xTb);
    cudaGetSymbolAddress((void**)&xcb,  g_xcb);
    cudaGetSymbolAddress((void**)&yb,   g_yb);
    cudaGetSymbolAddress((void**)&gub,  g_gub);
    cudaGetSymbolAddress((void**)&linb, g_linb);
    cudaGetSymbolAddress((void**)&inpb, g_inpb);
    cudaGetSymbolAddress((void**)&xpb,  g_xpb);
    cudaGetSymbolAddress((void**)&outpb,g_outpb);
    cudaGetSymbolAddress((void**)&gpb,  g_gpb);
    cudaGetSymbolAddress((void**)&upb,  g_upb);
    cudaGetSymbolAddress((void**)&dpb,  g_dpb);
    cudaGetSymbolAddress((void**)&hw1b, g_hw1b);

    static bool attr_set = false;
    if (!attr_set) {
        cudaFuncSetAttribute(gemm_bf, cudaFuncAttributeMaxDynamicSharedMemorySize, GEMM_SMEM);
        attr_set = true;
    }

    auto f2b = [&](const float* in, bf16* ob, int n) {
        f2b_kernel<<<(n / 4 + 255) / 256, 256>>>(in, ob, n);
    };
    // weight conversions
    f2b(lin_w,     linb,  DIM * DIM);
    f2b(in_proj_w, inpb,  NBLK * 2 * DI * DIM);
    f2b(x_proj_w,  xpb,   NBLK * 48 * DI);
    f2b(out_proj_w,outpb, NBLK * DIM * DI);
    f2b(gproj_w,   gpb,   NBLK * NE * INNER * DIM);
    f2b(uproj_w,   upb,   NBLK * NE * INNER * DIM);
    f2b(dproj_w,   dpb,   NBLK * NE * DIM * INNER);
    f2b(head_w1,   hw1b,  DIM * DIM);

    auto gemm = [&](const bf16* A, const bf16* W, float* C, bf16* Cb, const float* R,
                    const float* rs, int rsStride, int lda, int N, int K, int mode, int wMoE) {
        dim3 grid((N + BN - 1) / BN, LL / BM);
        gemm_bf<<<grid, 256, GEMM_SMEM>>>(A, W, C, Cb, R, rs, rsStride, lda, LL, N, K, mode, wMoE);
    };

    // h = x.T @ lin_w.T
    transpose_kernel<<<dim3(LL / 32, DIM / 32), dim3(32, 8)>>>(x, xTb);
    gemm(xTb, linb, h, hb, nullptr, nullptr, 0, DIM, DIM, DIM, 0, 0);

    for (int i = 0; i < NBLK; i++) {
        // ---- mamba ----
        rmsnorm_kernel<<<LL, DIM>>>(h, rms_a_w, nullptr, nullptr, hnb);
        gemm(hnb, inpb + (size_t)i * 2 * DI * DIM, xr, nullptr, nullptr, nullptr, 0,
             DIM, 2 * DI, DIM, 0, 0);
        conv_kernel<<<(LL * DI + 255) / 256, 256>>>(xr, conv_w + (size_t)i * DI * DCONV,
                                                    conv_b + (size_t)i * DI, xc, xcb);
        gemm(xcb, xpb + (size_t)i * 48 * DI, xdbl, nullptr, nullptr, nullptr, 0,
             DI, 48, DI, 0, 0);
        delta_kernel<<<LL, 256>>>(xdbl, dt_proj_w + (size_t)i * DI * DTR,
                                  dt_proj_b + (size_t)i * DI, delta);
        const float* Alog_i = A_log + (size_t)i * DI * NS;
        scan_p1<<<NCH * (DI / 8), 128>>>(delta, xc, xdbl, Alog_i, cs, sd);
        scan_p2<<<DI * NS / 256, 256>>>(Alog_i, cs, sd, init);
        scan_p3<<<NCH * (DI / 8), 128>>>(delta, xc, xdbl, Alog_i, init,
                                         D_param + (size_t)i * DI, xr, yb);
        // h = out_proj(y) + h (residual); also emit h bf16
        gemm(yb, outpb + (size_t)i * DIM * DI, h, hb, h, nullptr, 0, DI, DIM, DI, 2, 0);

        // ---- MoE ----
        gate_kernel<<<LL / 8, 256>>>(h, gate_w + (size_t)i * NE * DIM, w);
        // gf = h @ Gall^T (fp32 raw)
        gemm(hb, gpb + (size_t)i * NE * INNER * DIM, gf, nullptr, nullptr, nullptr, 0,
             DIM, NE * INNER, DIM, 0, 0);
        // gub = bf16( silu(gf) * (h @ Uall^T) * w[t,e] )
        gemm(hb, upb + (size_t)i * NE * INNER * DIM, gf, gub, nullptr, w, NE,
             DIM, NE * INNER, DIM, 6, 0);
        // moe = gub @ Dall^T (K=2048, expert-sliced)
        gemm(gub, dpb + (size_t)i * NE * DIM * INNER, moe, nullptr, nullptr, nullptr, 0,
             NE * INNER, DIM, NE * INNER, 0, 1);
        // h = rmsnorm(moe) + h; emit fp32 + bf16
        rmsnorm_kernel<<<LL, DIM>>>(moe, rms_f_w, h, h, hb);
    }

    // head
    gemm(hb, linb, nullptr, hnb, nullptr, nullptr, 0, DIM, DIM, DIM, 0, 0);
    gemm(hnb, hw1b, xT, nullptr, nullptr, nullptr, 0, DIM, DIM, DIM, 1, 0);
    head2_kernel<<<LL * HOR / 256, 256>>>(xT, head_w2, out);
}

// round 8
// speedup vs baseline: 1.2765x; 1.0495x over previous
#include <cuda_runtime.h>
#include <cuda_bf16.h>
#include <math.h>
#include <stdint.h>

#define LL    8192
#define DIM   256
#define DI    512
#define DCONV 4
#define NS    16
#define DTR   16
#define NE    4
#define INNER 512
#define HOR   32
#define NBLK  8
#define EPSV  1e-3f

#define NCH 128
#define CL  64

typedef __nv_bfloat16 bf16;
typedef __nv_bfloat162 bf162;

// ---------------- fp32 scratch ----------------
__device__ float g_h   [LL*DIM];
__device__ float g_xT  [LL*DIM];
__device__ float g_xr  [LL*2*DI];
__device__ float g_xc  [LL*DI];
__device__ float g_xdbl[LL*(DTR+2*NS)];
__device__ float g_delta[LL*DI];
__device__ float g_moe [LL*DIM];
__device__ float g_w   [LL*NE];
__device__ float g_cs  [NCH*DI*NS];
__device__ float g_sd  [NCH*DI];
__device__ float g_init[NCH*DI*NS];
// ---------------- bf16 activation scratch ----------------
__device__ bf16 g_hb  [LL*DIM];
__device__ bf16 g_hnb [LL*DIM];
__device__ bf16 g_xTb [LL*DIM];
__device__ bf16 g_xcb [LL*DI];
__device__ bf16 g_yb  [LL*DI];
__device__ bf16 g_gfb [LL*NE*INNER];   // MoE gate raw (bf16)
__device__ bf16 g_gub [LL*NE*INNER];
// ---------------- bf16 weights ----------------
__device__ bf16 g_linb [DIM*DIM];
__device__ bf16 g_inpb [NBLK*2*DI*DIM];
__device__ bf16 g_xpb  [NBLK*(DTR+2*NS)*DI];
__device__ bf16 g_outpb[NBLK*DIM*DI];
__device__ bf16 g_gpb  [NBLK*NE*INNER*DIM];
__device__ bf16 g_upb  [NBLK*NE*INNER*DIM];
__device__ bf16 g_dpb  [NBLK*NE*DIM*INNER];
__device__ bf16 g_hw1b [DIM*DIM];

__device__ __forceinline__ float siluf(float x) { return x / (1.f + expf(-x)); }

__device__ __forceinline__ void mma_bf16(float c[4], const unsigned int a[4], const unsigned int b[2]) {
    asm volatile("mma.sync.aligned.m16n8k16.row.col.f32.bf16.bf16.f32 "
        "{%0,%1,%2,%3}, {%4,%5,%6,%7}, {%8,%9}, {%0,%1,%2,%3};"
        : "+f"(c[0]), "+f"(c[1]), "+f"(c[2]), "+f"(c[3])
        : "r"(a[0]), "r"(a[1]), "r"(a[2]), "r"(a[3]), "r"(b[0]), "r"(b[1]));
}

__device__ __forceinline__ void ldm4(unsigned int r[4], unsigned int addr) {
    asm volatile("ldmatrix.sync.aligned.m8n8.x4.shared.b16 {%0,%1,%2,%3}, [%4];"
        : "=r"(r[0]), "=r"(r[1]), "=r"(r[2]), "=r"(r[3]) : "r"(addr));
}

__device__ __forceinline__ void cp_async16(void* dst, const void* src) {
    unsigned int d = (unsigned int)__cvta_generic_to_shared(dst);
    asm volatile("cp.async.cg.shared.global [%0], [%1], 16;\n" :: "r"(d), "l"(src));
}
__device__ __forceinline__ void cp_commit() { asm volatile("cp.async.commit_group;\n"); }
__device__ __forceinline__ void cp_wait0()  { asm volatile("cp.async.wait_group 0;\n"); }
__device__ __forceinline__ void cp_wait1()  { asm volatile("cp.async.wait_group 1;\n"); }

// ---------------- fp32 -> bf16 conversion ----------------
__global__ void f2b_kernel(const float* __restrict__ in, bf16* __restrict__ out, int n)
{
    int i = (blockIdx.x * blockDim.x + threadIdx.x) * 4;
    if (i < n) {
        float4 v = *(const float4*)(in + i);
        *(bf162*)(out + i)     = __float22bfloat162_rn(make_float2(v.x, v.y));
        *(bf162*)(out + i + 2) = __float22bfloat162_rn(make_float2(v.z, v.w));
    }
}

// ---------------- transpose x (DIM,L) -> xT (L,DIM) bf16 ----------------
__global__ void transpose_kernel(const float* __restrict__ x, bf16* __restrict__ xTb)
{
    __shared__ float tile[32][33];
    int bx = blockIdx.x * 32;
    int by = blockIdx.y * 32;
    int tx = threadIdx.x, ty = threadIdx.y;
    #pragma unroll
    for (int i = 0; i < 32; i += 8)
        tile[ty + i][tx] = x[(by + ty + i) * LL + bx + tx];
    __syncthreads();
    #pragma unroll
    for (int i = 0; i < 32; i += 8)
        xTb[(bx + ty + i) * DIM + by + tx] = __float2bfloat16(tile[tx][ty + i]);
}

// ---------------- bf16 tensor-core GEMM (ldmatrix): C = epi(A[M,K](lda) @ W[N,K]^T) ----------
// modes: 0 store, 1 silu store, 2 v+=R store, 6 Cb = bf16(silu(Gb)*v*rs[m*rsStride+(bn>>9)])
// wMoE: B is 4 expert slices dp[e][n][k&511], e = k>>9 (K = 2048)
#define BM 128
#define BN 64
#define BK 32
#define ST 20              // u32 row stride (16 data + 4 pad)
#define NSTG 3
#define GEMM_SMEM (NSTG*(BM+BN)*ST*4)

extern __shared__ unsigned int smem_u[];

__global__ __launch_bounds__(256)
void gemm_bf(const bf16* __restrict__ A, const bf16* __restrict__ W,
             float* __restrict__ C, bf16* __restrict__ Cb,
             const float* __restrict__ R, const bf16* __restrict__ Gb,
             const float* __restrict__ rs, int rsStride, int lda,
             int M, int N, int K, int mode, int wMoE)
{
    unsigned int* As = smem_u;                    // [NSTG][BM*ST]
    unsigned int* Bs = smem_u + NSTG * BM * ST;   // [NSTG][BN*ST]
    int bm = blockIdx.y * BM;
    int bn = blockIdx.x * BN;
    int tid = threadIdx.x;
    int lane = tid & 31;
    int warp = tid >> 5;
    int wm = (warp & 3) * 32;
    int wn = (warp >> 2) * 32;

    float acc[2][4][4];
    #pragma unroll
    for (int mt = 0; mt < 2; mt++)
        #pragma unroll
        for (int nt = 0; nt < 4; nt++)
            #pragma unroll
            for (int q = 0; q < 4; q++) acc[mt][nt][q] = 0.f;

    auto issue = [&](int k0, int st) {
        unsigned int* Ab = As + st * BM * ST;
        unsigned int* Bb = Bs + st * BN * ST;
        #pragma unroll
        for (int q = 0; q < 2; q++) {            // A: 128 rows x 4 granules = 512
            int g = q * 256 + tid;
            int r = g >> 2, c4 = g & 3;
            cp_async16(Ab + r * ST + c4 * 4,
                       A + (size_t)(bm + r) * lda + k0 + c4 * 8);
        }
        const bf16* Wb;
        int wst;
        if (wMoE) {
            int e = k0 >> 9;
            Wb = W + (size_t)e * DIM * INNER + (k0 & 511);
            wst = INNER;
        } else {
            Wb = W + k0;
            wst = K;
        }
        {                                         // B: 64 rows x 4 granules = 256
            int r = tid >> 2, c4 = tid & 3;
            int rn = bn + r; if (rn >= N) rn = N - 1;
            cp_async16(Bb + r * ST + c4 * 4,
                       Wb + (size_t)rn * wst + c4 * 8);
        }
        cp_commit();
    };

    int nsteps = K / BK;
    issue(0, 0);
    issue(BK, 1);

    // ldmatrix lane addressing (byte offsets within a stage)
    unsigned int smem_base = (unsigned int)__cvta_generic_to_shared(smem_u);
    int la = lane & 7;
    // A: matrix j = lane>>3: row += (j&1)*8, col(u32) += (j>>1)*4
    unsigned int aOff = ((unsigned int)((wm + la + ((lane >> 3) & 1) * 8) * ST
                         + ((lane >> 4) & 1) * 4)) * 4;
    // B: matrix j: row += (j>>1)*8, col(u32) += (j&1)*4
    unsigned int bOff = ((unsigned int)(NSTG * BM * ST
                         + (wn + la + ((lane >> 4) & 1) * 8) * ST
                         + ((lane >> 3) & 1) * 4)) * 4;

    for (int s = 0; s < nsteps; s++) {
        if (s + 1 < nsteps) cp_wait1(); else cp_wait0();
        __syncthreads();
        if (s + 2 < nsteps) issue((s + 2) * BK, (s + 2) % NSTG);

        int st = s % NSTG;
        unsigned int sa = smem_base + (unsigned int)(st * BM * ST) * 4 + aOff;
        unsigned int sb = smem_base + (unsigned int)(st * BN * ST) * 4 + bOff;
        #pragma unroll
        for (int kk = 0; kk < 2; kk++) {
            unsigned int koB = kk * 32;           // 8 u32 = 32 bytes
            unsigned int a0[4], a1[4], b0[4], b1[4];
            ldm4(a0, sa + koB);                   // mt0: m 0-15
            ldm4(a1, sa + 16 * ST * 4 + koB);     // mt1: m 16-31
            ldm4(b0, sb + koB);                   // nt0, nt1
            ldm4(b1, sb + 16 * ST * 4 + koB);     // nt2, nt3
            mma_bf16(acc[0][0], a0, b0 + 0);
            mma_bf16(acc[0][1], a0, b0 + 2);
            mma_bf16(acc[0][2], a0, b1 + 0);
            mma_bf16(acc[0][3], a0, b1 + 2);
            mma_bf16(acc[1][0], a1, b0 + 0);
            mma_bf16(acc[1][1], a1, b0 + 2);
            mma_bf16(acc[1][2], a1, b1 + 0);
            mma_bf16(acc[1][3], a1, b1 + 2);
        }
    }

    // epilogue
    int rq = lane >> 2;
    int cq = lane & 3;
    int cc = cq * 2;
    int eIdx = bn >> 9;
    #pragma unroll
    for (int mt = 0; mt < 2; mt++) {
        #pragma unroll
        for (int half = 0; half < 2; half++) {
            int m = bm + wm + mt * 16 + rq + half * 8;
            float rsv = (mode == 6) ? rs[m * rsStride + eIdx] : 0.f;
            #pragma unroll
            for (int nt = 0; nt < 4; nt++) {
                int n = bn + wn + nt * 8 + cc;
                if (n < N) {
                    size_t o = (size_t)m * N + n;
                    float v0 = acc[mt][nt][half * 2 + 0];
                    float v1 = acc[mt][nt][half * 2 + 1];
                    if (mode == 1) {
                        v0 = v0 / (1.f + expf(-v0));
                        v1 = v1 / (1.f + expf(-v1));
                    } else if (mode == 2) {
                        v0 += R[o]; v1 += R[o + 1];
                    } else if (mode == 6) {
                        bf162 gp = *(const bf162*)(Gb + o);
                        float g0 = __bfloat162float(gp.x);
                        float g1 = __bfloat162float(gp.y);
                        v0 = (g0 / (1.f + expf(-g0))) * v0 * rsv;
                        v1 = (g1 / (1.f + expf(-g1))) * v1 * rsv;
                    }
                    if (C) { C[o] = v0; C[o + 1] = v1; }
                    if (Cb)
                        *(bf162*)(Cb + o) = __float22bfloat162_rn(make_float2(v0, v1));
                }
            }
        }
    }
}

// ---------------- rmsnorm: fp32 out optional, bf16 out optional ----------------
__global__ void rmsnorm_kernel(const float* __restrict__ in, const float* __restrict__ w,
                               const float* __restrict__ addres,
                               float* __restrict__ out, bf16* __restrict__ outb)
{
    int l = blockIdx.x;
    int t = threadIdx.x;
    float v = in[l * DIM + t];
    __shared__ float red[8];
    float s = v * v;
    #pragma unroll
    for (int o = 16; o > 0; o >>= 1) s += __shfl_xor_sync(0xffffffffu, s, o);
    if ((t & 31) == 0) red[t >> 5] = s;
    __syncthreads();
    if (t < 8) {
        float x2 = red[t];
        #pragma unroll
        for (int o = 4; o > 0; o >>= 1) x2 += __shfl_xor_sync(0xffu, x2, o);
        if (t == 0) red[0] = x2;
    }
    __syncthreads();
    float rms = rsqrtf(red[0] / (float)DIM + EPSV);
    float r = w[t] * v * rms;
    if (addres) r += addres[l * DIM + t];
    if (out)  out[l * DIM + t] = r;
    if (outb) outb[l * DIM + t] = __float2bfloat16(r);
}

// ---------------- causal depthwise conv(4) + bias + silu (fp32 + bf16 out) ----------------
__global__ void conv_kernel(const float* __restrict__ xr, const float* __restrict__ cw,
                            const float* __restrict__ cb,
                            float* __restrict__ xc, bf16* __restrict__ xcb)
{
    int idx = blockIdx.x * blockDim.x + threadIdx.x;
    if (idx >= LL * DI) return;
    int c = idx % DI, l = idx / DI;
    float w0 = cw[c * 4 + 0], w1 = cw[c * 4 + 1], w2 = cw[c * 4 + 2], w3 = cw[c * 4 + 3];
    float acc = cb[c];
    if (l >= 3) acc += xr[(size_t)(l - 3) * (2 * DI) + c] * w0;
    if (l >= 2) acc += xr[(size_t)(l - 2) * (2 * DI) + c] * w1;
    if (l >= 1) acc += xr[(size_t)(l - 1) * (2 * DI) + c] * w2;
    acc += xr[(size_t)l * (2 * DI) + c] * w3;
    float r = siluf(acc);
    xc[idx] = r;
    xcb[idx] = __float2bfloat16(r);
}

// ---------------- delta = softplus(dr @ dtw^T + dtb) ----------------
__global__ void delta_kernel(const float* __restrict__ xdbl, const float* __restrict__ dtw,
                             const float* __restrict__ dtb, float* __restrict__ delta)
{
    int l = blockIdx.x;
    __shared__ float dr[DTR];
    if (threadIdx.x < DTR) dr[threadIdx.x] = xdbl[l * 48 + threadIdx.x];
    __syncthreads();
    for (int d = threadIdx.x; d < DI; d += blockDim.x) {
        float acc = dtb[d];
        #pragma unroll
        for (int r = 0; r < DTR; r++) acc += dr[r] * dtw[d * DTR + r];
        float sp = (acc > 20.f) ? acc : log1pf(expf(acc));
        delta[(size_t)l * DI + d] = sp;
    }
}

// ---------------- gate: scores, top-2 softmax weights ----------------
__global__ void gate_kernel(const float* __restrict__ h, const float* __restrict__ gw,
                            float* __restrict__ wout)
{
    __shared__ float sgw[NE * DIM];
    int tid = threadIdx.x;
    for (int i = tid; i < NE * DIM; i += 256) sgw[i] = gw[i];
    __syncthreads();
    int warp = tid >> 5, lane = tid & 31;
    int t = blockIdx.x * 8 + warp;
    float acc[NE] = {0.f, 0.f, 0.f, 0.f};
    for (int k = lane; k < DIM; k += 32) {
        float hv = h[(size_t)t * DIM + k];
        #pragma unroll
        for (int e = 0; e < NE; e++) acc[e] += hv * sgw[e * DIM + k];
    }
    #pragma unroll
    for (int e = 0; e < NE; e++)
        #pragma unroll
        for (int o = 16; o > 0; o >>= 1) acc[e] += __shfl_xor_sync(0xffffffffu, acc[e], o);
    if (lane == 0) {
        int i1 = 0; float v1 = acc[0];
        for (int e = 1; e < NE; e++) if (acc[e] > v1) { v1 = acc[e]; i1 = e; }
        int i2 = -1; float v2 = -1e30f;
        for (int e = 0; e < NE; e++) if (e != i1 && acc[e] > v2) { v2 = acc[e]; i2 = e; }
        float ew = expf(v2 - v1);
        float w1 = 1.f / (1.f + ew), w2 = ew / (1.f + ew);
        float w[NE] = {0.f, 0.f, 0.f, 0.f};
        w[i1] = w1; w[i2] = w2;
        #pragma unroll
        for (int e = 0; e < NE; e++) wout[t * NE + e] = w[e];
    }
}

// ---------------- chunked selective scan ----------------
__global__ void scan_p1(const float* __restrict__ delta, const float* __restrict__ xc,
                        const float* __restrict__ xdbl, const float* __restrict__ Alog,
                        float* __restrict__ cs, float* __restrict__ sd)
{
    int b = blockIdx.x;
    int chunk = b >> 6;
    int dg = b & 63;
    int tid = threadIdx.x;
    int dl = tid >> 4, n = tid & 15;
    int d = dg * 8 + dl;
    float Acoef = -__expf(Alog[d * NS + n]);
    float s = 0.f, sdl = 0.f;
    int l0 = chunk * CL;
    for (int i = 0; i < CL; i++) {
        int l = l0 + i;
        float dt = delta[(size_t)l * DI + d];
        float x  = xc[(size_t)l * DI + d];
        float Bv = xdbl[l * 48 + DTR + n];
        s = __expf(dt * Acoef) * s + dt * Bv * x;
        sdl += dt;
    }
    cs[((size_t)chunk * DI + d) * NS + n] = s;
    if (n == 0) sd[chunk * DI + d] = sdl;
}

__global__ void scan_p2(const float* __restrict__ Alog, const float* __restrict__ cs,
                        const float* __restrict__ sd, float* __restrict__ init)
{
    int idx = blockIdx.x * blockDim.x + threadIdx.x;
    int d = idx >> 4, n = idx & 15;
    float Acoef = -__expf(Alog[d * NS + n]);
    float S = 0.f;
    for (int c = 0; c < NCH; c++) {
        init[((size_t)c * DI + d) * NS + n] = S;
        S = __expf(Acoef * sd[c * DI + d]) * S + cs[((size_t)c * DI + d) * NS + n];
    }
}

__global__ void scan_p3(const float* __restrict__ delta, const float* __restrict__ xc,
                        const float* __restrict__ xdbl, const float* __restrict__ Alog,
                        const float* __restrict__ init, const float* __restrict__ Dp,
                        const float* __restrict__ xr, bf16* __restrict__ yb)
{
    int b = blockIdx.x;
    int chunk = b >> 6;
    int dg = b & 63;
    int tid = threadIdx.x;
    int dl = tid >> 4, n = tid & 15;
    int d = dg * 8 + dl;
    float Acoef = -__expf(Alog[d * NS + n]);
    float s = init[((size_t)chunk * DI + d) * NS + n];
    float Dv = Dp[d];
    int l0 = chunk * CL;
    for (int i = 0; i < CL; i++) {
        int l = l0 + i;
        float dt = delta[(size_t)l * DI + d];
        float x  = xc[(size_t)l * DI + d];
        float Bv = xdbl[l * 48 + DTR + n];
        float Cv = xdbl[l * 48 + DTR + NS + n];
        s = __expf(dt * Acoef) * s + dt * Bv * x;
        float part = s * Cv;
        #pragma unroll
        for (int o = 1; o < 16; o <<= 1)
            part += __shfl_xor_sync(0xffffffffu, part, o, 16);
        if (n == 0) {
            float res = xr[(size_t)l * (2 * DI) + DI + d];
            yb[(size_t)l * DI + d] = __float2bfloat16((part + x * Dv) * siluf(res));
        }
    }
}

// ---------------- head2 ----------------
__global__ void head2_kernel(const float* __restrict__ a, const float* __restrict__ w2,
                             float* __restrict__ out)
{
    int idx = blockIdx.x * blockDim.x + threadIdx.x;
    int o = idx & 31, l = idx >> 5;
    const float* ar = a + (size_t)l * DIM;
    const float* wr = w2 + (size_t)o * DIM;
    float acc = 0.f;
    #pragma unroll 8
    for (int k = 0; k < DIM; k++) acc += ar[k] * wr[k];
    out[(size_t)o * LL + l] = 1.f / (1.f + expf(-acc));
}

// ---------------- host orchestration ----------------
extern "C" void kernel_launch(void* const* d_in, const int* in_sizes, int n_in,
                              void* d_out, int out_size)
{
    const float* x         = (const float*)d_in[0];
    const float* lin_w     = (const float*)d_in[1];
    const float* in_proj_w = (const float*)d_in[2];
    const float* conv_w    = (const float*)d_in[3];
    const float* conv_b    = (const float*)d_in[4];
    const float* x_proj_w  = (const float*)d_in[5];
    const float* dt_proj_w = (const float*)d_in[6];
    const float* dt_proj_b = (const float*)d_in[7];
    const float* A_log     = (const float*)d_in[8];
    const float* D_param   = (const float*)d_in[9];
    const float* out_proj_w= (const float*)d_in[10];
    const float* gate_w    = (const float*)d_in[11];
    const float* gproj_w   = (const float*)d_in[12];
    const float* uproj_w   = (const float*)d_in[13];
    const float* dproj_w   = (const float*)d_in[14];
    const float* rms_a_w   = (const float*)d_in[15];
    const float* rms_f_w   = (const float*)d_in[16];
    const float* head_w1   = (const float*)d_in[17];
    const float* head_w2   = (const float*)d_in[18];
    float* out = (float*)d_out;

    float *h, *xT, *xr, *xc, *xdbl, *delta, *moe, *w, *cs, *sd, *init;
    bf16 *hb, *hnb, *xTb, *xcb, *yb, *gfb, *gub;
    bf16 *linb, *inpb, *xpb, *outpb, *gpb, *upb, *dpb, *hw1b;
    cudaGetSymbolAddress((void**)&h,    g_h);
    cudaGetSymbolAddress((void**)&xT,   g_xT);
    cudaGetSymbolAddress((void**)&xr,   g_xr);
    cudaGetSymbolAddress((void**)&xc,   g_xc);
    cudaGetSymbolAddress((void**)&xdbl, g_xdbl);
    cudaGetSymbolAddress((void**)&delta,g_delta);
    cudaGetSymbolAddress((void**)&moe,  g_moe);
    cudaGetSymbolAddress((void**)&w,    g_w);
    cudaGetSymbolAddress((void**)&cs,   g_cs);
    cudaGetSymbolAddress((void**)&sd,   g_sd);
    cudaGetSymbolAddress((void**)&init, g_init);
    cudaGetSymbolAddress((void**)&hb,   g_hb);
    cudaGetSymbolAddress((void**)&hnb,  g_hnb);
    cudaGetSymbolAddress((void**)&xTb,  g_xTb);
    cudaGetSymbolAddress((void**)&xcb,  g_xcb);
    cudaGetSymbolAddress((void**)&yb,   g_yb);
    cudaGetSymbolAddress((void**)&gfb,  g_gfb);
    cudaGetSymbolAddress((void**)&gub,  g_gub);
    cudaGetSymbolAddress((void**)&linb, g_linb);
    cudaGetSymbolAddress((void**)&inpb, g_inpb);
    cudaGetSymbolAddress((void**)&xpb,  g_xpb);
    cudaGetSymbolAddress((void**)&outpb,g_outpb);
    cudaGetSymbolAddress((void**)&gpb,  g_gpb);
    cudaGetSymbolAddress((void**)&upb,  g_upb);
    cudaGetSymbolAddress((void**)&dpb,  g_dpb);
    cudaGetSymbolAddress((void**)&hw1b, g_hw1b);

    static bool attr_set = false;
    if (!attr_set) {
        cudaFuncSetAttribute(gemm_bf, cudaFuncAttributeMaxDynamicSharedMemorySize, GEMM_SMEM);
        attr_set = true;
    }

    auto f2b = [&](const float* in, bf16* ob, int n) {
        f2b_kernel<<<(n / 4 + 255) / 256, 256>>>(in, ob, n);
    };
    f2b(lin_w,     linb,  DIM * DIM);
    f2b(in_proj_w, inpb,  NBLK * 2 * DI * DIM);
    f2b(x_proj_w,  xpb,   NBLK * 48 * DI);
    f2b(out_proj_w,outpb, NBLK * DIM * DI);
    f2b(gproj_w,   gpb,   NBLK * NE * INNER * DIM);
    f2b(uproj_w,   upb,   NBLK * NE * INNER * DIM);
    f2b(dproj_w,   dpb,   NBLK * NE * DIM * INNER);
    f2b(head_w1,   hw1b,  DIM * DIM);

    auto gemm = [&](const bf16* A, const bf16* W, float* C, bf16* Cb, const float* R,
                    const bf16* Gb, const float* rs, int rsStride, int lda,
                    int N, int K, int mode, int wMoE) {
        dim3 grid((N + BN - 1) / BN, LL / BM);
        gemm_bf<<<grid, 256, GEMM_SMEM>>>(A, W, C, Cb, R, Gb, rs, rsStride, lda,
                                          LL, N, K, mode, wMoE);
    };

    // h = x.T @ lin_w.T
    transpose_kernel<<<dim3(LL / 32, DIM / 32), dim3(32, 8)>>>(x, xTb);
    gemm(xTb, linb, h, hb, nullptr, nullptr, nullptr, 0, DIM, DIM, DIM, 0, 0);

    for (int i = 0; i < NBLK; i++) {
        // ---- mamba ----
        rmsnorm_kernel<<<LL, DIM>>>(h, rms_a_w, nullptr, nullptr, hnb);
        gemm(hnb, inpb + (size_t)i * 2 * DI * DIM, xr, nullptr, nullptr, nullptr,
             nullptr, 0, DIM, 2 * DI, DIM, 0, 0);
        conv_kernel<<<(LL * DI + 255) / 256, 256>>>(xr, conv_w + (size_t)i * DI * DCONV,
                                                    conv_b + (size_t)i * DI, xc, xcb);
        gemm(xcb, xpb + (size_t)i * 48 * DI, xdbl, nullptr, nullptr, nullptr,
             nullptr, 0, DI, 48, DI, 0, 0);
        delta_kernel<<<LL, 256>>>(xdbl, dt_proj_w + (size_t)i * DI * DTR,
                                  dt_proj_b + (size_t)i * DI, delta);
        const float* Alog_i = A_log + (size_t)i * DI * NS;
        scan_p1<<<NCH * (DI / 8), 128>>>(delta, xc, xdbl, Alog_i, cs, sd);
        scan_p2<<<DI * NS / 256, 256>>>(Alog_i, cs, sd, init);
        scan_p3<<<NCH * (DI / 8), 128>>>(delta, xc, xdbl, Alog_i, init,
                                         D_param + (size_t)i * DI, xr, yb);
        // h = out_proj(y) + h (residual); emit h bf16
        gemm(yb, outpb + (size_t)i * DIM * DI, h, hb, h, nullptr, nullptr, 0,
             DI, DIM, DI, 2, 0);

        // ---- MoE ----
        gate_kernel<<<LL / 8, 256>>>(h, gate_w + (size_t)i * NE * DIM, w);
        // gfb = bf16(h @ Gall^T)
        gemm(hb, gpb + (size_t)i * NE * INNER * DIM, nullptr, gfb, nullptr, nullptr,
             nullptr, 0, DIM, NE * INNER, DIM, 0, 0);
        // gub = bf16( silu(gfb) * (h @ Uall^T) * w[t,e] )
        gemm(hb, upb + (size_t)i * NE * INNER * DIM, nullptr, gub, nullptr, gfb,
             w, NE, DIM, NE * INNER, DIM, 6, 0);
        // moe = gub @ Dall^T (K=2048, expert-sliced)
        gemm(gub, dpb + (size_t)i * NE * DIM * INNER, moe, nullptr, nullptr, nullptr,
             nullptr, 0, NE * INNER, DIM, NE * INNER, 0, 1);
        // h = rmsnorm(moe) + h; emit fp32 + bf16
        rmsnorm_kernel<<<LL, DIM>>>(moe, rms_f_w, h, h, hb);
    }

    // head
    gemm(hb, linb, nullptr, hnb, nullptr, nullptr, nullptr, 0, DIM, DIM, DIM, 0, 0);
    gemm(hnb, hw1b, xT, nullptr, nullptr, nullptr, nullptr, 0, DIM, DIM, DIM, 1, 0);
    head2_kernel<<<LL * HOR / 256, 256>>>(xT, head_w2, out);
}